// round 10
// baseline (speedup 1.0000x reference)
#include <cuda_runtime.h>
#include <cuda_bf16.h>
#include <cstdint>

// GCN layer: out = (scatter_mean(x[col] -> row)) @ W^T + b
// N_NODES=100000, N_EDGES=1600000, IN=OUT=64 (dims hardcoded to 64, counts dynamic)

#define DIM 64
#define MAX_NODES 100000

// device scratch (no allocations allowed)
__device__ int g_deg[MAX_NODES];
__device__ int g_idx_is64;   // 1 if edge_index is int64, 0 if int32

// ---------------------------------------------------------------------------
// Kernel 0: sniff edge_index dtype. int64 values < 2^31 (node ids < 1e5)
// have every odd 32-bit word == 0. Random int32 node ids do not.
// ---------------------------------------------------------------------------
__global__ void sniff_kernel(const int* __restrict__ e_words) {
    if (threadIdx.x == 0 && blockIdx.x == 0) {
        int is64 = 1;
        #pragma unroll
        for (int i = 1; i < 64; i += 2) {
            if (e_words[i] != 0) { is64 = 0; break; }
        }
        g_idx_is64 = is64;
    }
}

// ---------------------------------------------------------------------------
// Kernel 1: zero the accumulator (d_out) and the degree array
// ---------------------------------------------------------------------------
__global__ void zero_kernel(float4* __restrict__ out4, int n4, int n_nodes) {
    int i = blockIdx.x * blockDim.x + threadIdx.x;
    if (i < n4) out4[i] = make_float4(0.f, 0.f, 0.f, 0.f);
    if (i < n_nodes) g_deg[i] = 0;
}

// ---------------------------------------------------------------------------
// Kernel 2: edge scatter. 16 threads per edge; each lane handles one float4
// chunk (16 lanes * 16B = 64 floats). 128-bit vector atomicAdd (sm_90+
// intrinsic -> single REDG.128, no return-value use).
// ---------------------------------------------------------------------------
__global__ void __launch_bounds__(256) edge_scatter_kernel(
    const void* __restrict__ e_base,       // edge_index raw base
    const float4* __restrict__ x4,         // [n_nodes][16] float4
    float4* __restrict__ out4,             // [n_nodes][16] float4 accumulator
    int n_edges)
{
    int idx  = blockIdx.x * blockDim.x + threadIdx.x;
    int e    = idx >> 4;
    int lane = idx & 15;
    if (e >= n_edges) return;

    int r, c;
    if (g_idx_is64) {
        const long long* e64 = (const long long*)e_base;
        r = (int)__ldg(e64 + e);
        c = (int)__ldg(e64 + n_edges + e);
    } else {
        const int* e32 = (const int*)e_base;
        r = __ldg(e32 + e);
        c = __ldg(e32 + n_edges + e);
    }

    float4 v = __ldg(x4 + (c * 16 + lane));
#if defined(__CUDA_ARCH__) && (__CUDA_ARCH__ >= 900)
    atomicAdd(out4 + (r * 16 + lane), v);          // 128-bit vector red
#else
    float* dst = (float*)(out4 + (r * 16 + lane));
    atomicAdd(dst + 0, v.x);
    atomicAdd(dst + 1, v.y);
    atomicAdd(dst + 2, v.z);
    atomicAdd(dst + 3, v.w);
#endif
    if (lane == 0) {
        atomicAdd(&g_deg[r], 1);
    }
}

// ---------------------------------------------------------------------------
// Kernel 3: per-row transform: out[row] = (acc[row]/max(deg,1)) @ W^T + b
// 256 threads = 4 rows per iteration, grid-stride over rows.
// W transposed into shared: Wt[k*64+j] = W[j*64+k]  -> conflict-free reads.
// ---------------------------------------------------------------------------
__global__ void __launch_bounds__(256) transform_kernel(
    float* __restrict__ out,               // in: acc, out: final  [n_nodes][64]
    const float* __restrict__ W,           // [64][64] row-major (OUT, IN)
    const float* __restrict__ b,           // [64]
    int n_nodes)
{
    __shared__ float Wt[DIM * DIM];   // 16 KB
    __shared__ float bsh[DIM];
    __shared__ float rows[4 * DIM];   // 1 KB

    int tid = threadIdx.x;
    // load + transpose W, load b (once per block)
    #pragma unroll
    for (int i = tid; i < DIM * DIM; i += 256) {
        int j = i >> 6, k = i & 63;
        Wt[k * DIM + j] = W[i];
    }
    if (tid < DIM) bsh[tid] = b[tid];
    __syncthreads();

    int g = tid >> 6;          // row group 0..3
    int j = tid & 63;          // output feature

    for (int base = blockIdx.x * 4; base < n_nodes; base += gridDim.x * 4) {
        int row = base + g;
        if (row < n_nodes) {
            int d = g_deg[row];
            float invd = (d > 1) ? __frcp_rn((float)d) : 1.0f;
            rows[tid] = out[row * DIM + j] * invd;
        }
        __syncthreads();
        if (row < n_nodes) {
            float s = bsh[j];
            const float* a = rows + g * DIM;
            #pragma unroll
            for (int k = 0; k < DIM; k++) {
                s = fmaf(a[k], Wt[k * DIM + j], s);
            }
            out[row * DIM + j] = s;
        }
        __syncthreads();
    }
}

// ---------------------------------------------------------------------------
// Launcher
// ---------------------------------------------------------------------------
extern "C" void kernel_launch(void* const* d_in, const int* in_sizes, int n_in,
                              void* d_out, int out_size)
{
    const float* x  = (const float*)d_in[0];        // [n_nodes, 64]
    const void*  ei = d_in[1];                      // [2, n_edges] int32 or int64
    const float* W  = (const float*)d_in[2];        // [64, 64]
    const float* b  = (const float*)d_in[3];        // [64]
    float*       out = (float*)d_out;               // [n_nodes, 64]

    int n_nodes = in_sizes[0] / DIM;
    int n_edges = in_sizes[1] / 2;

    // 0) dtype sniff (1 thread, trivial cost)
    sniff_kernel<<<1, 32>>>((const int*)ei);

    // 1) zero accumulator + degrees
    int n4 = n_nodes * (DIM / 4);       // 1.6M float4
    {
        int threads = 256;
        int blocks = (n4 + threads - 1) / threads;
        zero_kernel<<<blocks, threads>>>((float4*)out, n4, n_nodes);
    }

    // 2) edge scatter
    {
        long long total = (long long)n_edges * 16;
        int threads = 256;
        int blocks = (int)((total + threads - 1) / threads);
        edge_scatter_kernel<<<blocks, threads>>>(
            ei, (const float4*)x, (float4*)out, n_edges);
    }

    // 3) transform (in-place on d_out)
    {
        int threads = 256;
        int blocks = 148 * 8;   // grid-stride; keeps W reload traffic tiny
        transform_kernel<<<blocks, threads>>>(out, W, b, n_nodes);
    }
}

// round 11
// speedup vs baseline: 1.1086x; 1.1086x over previous
#include <cuda_runtime.h>
#include <cuda_bf16.h>
#include <cstdint>

// GCN layer: out = (scatter_mean(x[col] -> row)) @ W^T + b
// N_NODES=100000, N_EDGES=1600000, IN=OUT=64 (dims hardcoded to 64, counts dynamic)

#define DIM 64
#define MAX_NODES 100000

// device scratch (no allocations allowed)
__device__ int g_deg[MAX_NODES];
__device__ int g_idx_is64;   // 1 if edge_index is int64, 0 if int32

// ---------------------------------------------------------------------------
// Kernel 0: sniff edge_index dtype. int64 values < 2^31 (node ids < 1e5)
// have every odd 32-bit word == 0. Random int32 node ids do not.
// ---------------------------------------------------------------------------
__global__ void sniff_kernel(const int* __restrict__ e_words) {
    if (threadIdx.x == 0 && blockIdx.x == 0) {
        int is64 = 1;
        #pragma unroll
        for (int i = 1; i < 64; i += 2) {
            if (e_words[i] != 0) { is64 = 0; break; }
        }
        g_idx_is64 = is64;
    }
}

// ---------------------------------------------------------------------------
// Kernel 1: zero the accumulator (d_out) and the degree array
// ---------------------------------------------------------------------------
__global__ void zero_kernel(float4* __restrict__ out4, int n4, int n_nodes) {
    int i = blockIdx.x * blockDim.x + threadIdx.x;
    if (i < n4) out4[i] = make_float4(0.f, 0.f, 0.f, 0.f);
    if (i < n_nodes) g_deg[i] = 0;
}

// ---------------------------------------------------------------------------
// Kernel 2: edge scatter. 16 threads per edge; each lane handles one float4
// chunk (16 lanes * 16B = 64 floats). 128-bit vector atomicAdd (sm_90+
// intrinsic -> single REDG.128, no return-value use).
// ---------------------------------------------------------------------------
__global__ void __launch_bounds__(256) edge_scatter_kernel(
    const void* __restrict__ e_base,       // edge_index raw base
    const float4* __restrict__ x4,         // [n_nodes][16] float4
    float4* __restrict__ out4,             // [n_nodes][16] float4 accumulator
    int n_edges)
{
    int idx  = blockIdx.x * blockDim.x + threadIdx.x;
    int e    = idx >> 4;
    int lane = idx & 15;
    if (e >= n_edges) return;

    int r, c;
    if (g_idx_is64) {
        const long long* e64 = (const long long*)e_base;
        r = (int)__ldg(e64 + e);
        c = (int)__ldg(e64 + n_edges + e);
    } else {
        const int* e32 = (const int*)e_base;
        r = __ldg(e32 + e);
        c = __ldg(e32 + n_edges + e);
    }

    float4 v = __ldg(x4 + (c * 16 + lane));
#if defined(__CUDA_ARCH__) && (__CUDA_ARCH__ >= 900)
    atomicAdd(out4 + (r * 16 + lane), v);          // 128-bit vector red
#else
    float* dst = (float*)(out4 + (r * 16 + lane));
    atomicAdd(dst + 0, v.x);
    atomicAdd(dst + 1, v.y);
    atomicAdd(dst + 2, v.z);
    atomicAdd(dst + 3, v.w);
#endif
    if (lane == 0) {
        atomicAdd(&g_deg[r], 1);
    }
}

// ---------------------------------------------------------------------------
// Kernel 3: per-row transform: out[row] = (acc[row]/max(deg,1)) @ W^T + b
// Register-resident W: each thread owns output column j = tid&63 and keeps
// all 64 W[j][k] in registers. Activation rows staged in shared, read as
// float4 BROADCASTS (conflict-free, N=1). FFMA-issue bound (~24us floor).
// Grid is fixed small (296 blocks) so per-block W reload traffic stays tiny.
// ---------------------------------------------------------------------------
__global__ void __launch_bounds__(256) transform_kernel(
    float* __restrict__ out,               // in: acc, out: final  [n_nodes][64]
    const float* __restrict__ W,           // [64][64] row-major (OUT, IN)
    const float* __restrict__ b,           // [64]
    int n_nodes)
{
    __shared__ float4 rows4[4 * 16];       // 4 rows x 64 floats
    float* rows = (float*)rows4;

    int tid = threadIdx.x;
    int g = tid >> 6;          // row group 0..3
    int j = tid & 63;          // output feature

    // W column j -> registers (once per block)
    float w[DIM];
    const float4* Wj = (const float4*)(W + j * DIM);
    #pragma unroll
    for (int k4 = 0; k4 < 16; k4++) {
        float4 t = __ldg(Wj + k4);
        w[k4 * 4 + 0] = t.x;
        w[k4 * 4 + 1] = t.y;
        w[k4 * 4 + 2] = t.z;
        w[k4 * 4 + 3] = t.w;
    }
    float bj = __ldg(b + j);

    int stride = gridDim.x * 4;
    for (int base = blockIdx.x * 4; base < n_nodes; base += stride) {
        int row = base + g;
        bool ok = (row < n_nodes);
        if (ok) {
            int d = g_deg[row];
            float invd = (d > 1) ? __frcp_rn((float)d) : 1.0f;
            rows[tid] = out[row * DIM + j] * invd;   // coalesced 128B/warp
        }
        __syncthreads();
        if (ok) {
            float s = bj;
            #pragma unroll
            for (int k4 = 0; k4 < 16; k4++) {
                float4 a = rows4[g * 16 + k4];       // LDS.128 broadcast
                s = fmaf(a.x, w[k4 * 4 + 0], s);
                s = fmaf(a.y, w[k4 * 4 + 1], s);
                s = fmaf(a.z, w[k4 * 4 + 2], s);
                s = fmaf(a.w, w[k4 * 4 + 3], s);
            }
            out[row * DIM + j] = s;                  // coalesced
        }
        __syncthreads();
    }
}

// ---------------------------------------------------------------------------
// Launcher
// ---------------------------------------------------------------------------
extern "C" void kernel_launch(void* const* d_in, const int* in_sizes, int n_in,
                              void* d_out, int out_size)
{
    const float* x  = (const float*)d_in[0];        // [n_nodes, 64]
    const void*  ei = d_in[1];                      // [2, n_edges] int32 or int64
    const float* W  = (const float*)d_in[2];        // [64, 64]
    const float* b  = (const float*)d_in[3];        // [64]
    float*       out = (float*)d_out;               // [n_nodes, 64]

    int n_nodes = in_sizes[0] / DIM;
    int n_edges = in_sizes[1] / 2;

    // 0) dtype sniff (1 thread, trivial cost)
    sniff_kernel<<<1, 32>>>((const int*)ei);

    // 1) zero accumulator + degrees
    int n4 = n_nodes * (DIM / 4);       // 1.6M float4
    {
        int threads = 256;
        int blocks = (n4 + threads - 1) / threads;
        zero_kernel<<<blocks, threads>>>((float4*)out, n4, n_nodes);
    }

    // 2) edge scatter
    {
        long long total = (long long)n_edges * 16;
        int threads = 256;
        int blocks = (int)((total + threads - 1) / threads);
        edge_scatter_kernel<<<blocks, threads>>>(
            ei, (const float4*)x, (float4*)out, n_edges);
    }

    // 3) transform (in-place on d_out), fixed small grid: 2 blocks/SM
    {
        int threads = 256;
        int blocks = 148 * 2;
        transform_kernel<<<blocks, threads>>>(out, W, b, n_nodes);
    }
}

// round 12
// speedup vs baseline: 1.3462x; 1.2144x over previous
#include <cuda_runtime.h>
#include <cuda_bf16.h>
#include <cstdint>

// GCN layer: out = (scatter_mean(x[col] -> row)) @ W^T + b
// N_NODES=100000, N_EDGES=1600000, IN=OUT=64

#define DIM 64
#define MAX_NODES 100000
#define ROWS_PER_ITER 32          // rows staged per block iteration
#define ROWS_PER_THREAD 8         // ROWS_PER_ITER / 4 groups

// device scratch (no allocations allowed)
__device__ int g_deg[MAX_NODES];
__device__ int g_idx_is64;   // 1 if edge_index is int64, 0 if int32

// ---------------------------------------------------------------------------
// Kernel 0: sniff edge_index dtype. int64 values < 2^31 (node ids < 1e5)
// have every odd 32-bit word == 0. Random int32 node ids do not.
// ---------------------------------------------------------------------------
__global__ void sniff_kernel(const int* __restrict__ e_words) {
    if (threadIdx.x == 0 && blockIdx.x == 0) {
        int is64 = 1;
        #pragma unroll
        for (int i = 1; i < 64; i += 2) {
            if (e_words[i] != 0) { is64 = 0; break; }
        }
        g_idx_is64 = is64;
    }
}

// ---------------------------------------------------------------------------
// Kernel 1: zero the accumulator (d_out) and the degree array
// ---------------------------------------------------------------------------
__global__ void zero_kernel(float4* __restrict__ out4, int n4, int n_nodes) {
    int i = blockIdx.x * blockDim.x + threadIdx.x;
    if (i < n4) out4[i] = make_float4(0.f, 0.f, 0.f, 0.f);
    if (i < n_nodes) g_deg[i] = 0;
}

// ---------------------------------------------------------------------------
// Kernel 2: edge scatter. 16 threads per edge; each lane handles one float4
// chunk. 128-bit vector atomicAdd -> single REDG.128.
// ---------------------------------------------------------------------------
__global__ void __launch_bounds__(256) edge_scatter_kernel(
    const void* __restrict__ e_base,       // edge_index raw base
    const float4* __restrict__ x4,         // [n_nodes][16] float4
    float4* __restrict__ out4,             // [n_nodes][16] float4 accumulator
    int n_edges)
{
    int idx  = blockIdx.x * blockDim.x + threadIdx.x;
    int e    = idx >> 4;
    int lane = idx & 15;
    if (e >= n_edges) return;

    int r, c;
    if (g_idx_is64) {
        const long long* e64 = (const long long*)e_base;
        r = (int)__ldg(e64 + e);
        c = (int)__ldg(e64 + n_edges + e);
    } else {
        const int* e32 = (const int*)e_base;
        r = __ldg(e32 + e);
        c = __ldg(e32 + n_edges + e);
    }

    float4 v = __ldg(x4 + (c * 16 + lane));
#if defined(__CUDA_ARCH__) && (__CUDA_ARCH__ >= 900)
    atomicAdd(out4 + (r * 16 + lane), v);          // 128-bit vector red
#else
    float* dst = (float*)(out4 + (r * 16 + lane));
    atomicAdd(dst + 0, v.x);
    atomicAdd(dst + 1, v.y);
    atomicAdd(dst + 2, v.z);
    atomicAdd(dst + 3, v.w);
#endif
    if (lane == 0) {
        atomicAdd(&g_deg[r], 1);
    }
}

// ---------------------------------------------------------------------------
// Kernel 3: transform out[row] = (acc[row]/max(deg,1)) @ W^T + b
//
// Register-resident W (thread owns column j = tid&63, all 64 W[j][k] in regs).
// 32 rows staged per iteration via 2 coalesced LDG.128/thread (deg scaling
// applied at staging). Each thread then computes 8 rows x 64 FFMA with
// LDS.128 broadcasts, 2 partial accumulators per row for ILP.
// ---------------------------------------------------------------------------
__global__ void __launch_bounds__(256) transform_kernel(
    float* __restrict__ out,               // in: acc, out: final  [n_nodes][64]
    const float* __restrict__ W,           // [64][64] row-major (OUT, IN)
    const float* __restrict__ b,           // [64]
    int n_nodes)
{
    __shared__ float4 rows4[ROWS_PER_ITER * 16];   // 32 rows x 64 floats = 8KB

    int tid = threadIdx.x;
    int g   = tid >> 6;        // group 0..3 -> rows [g*8, g*8+8)
    int j   = tid & 63;        // output feature

    // W row j -> registers (once per block)
    float w[DIM];
    const float4* Wj = (const float4*)(W + j * DIM);
    #pragma unroll
    for (int k4 = 0; k4 < 16; k4++) {
        float4 t = __ldg(Wj + k4);
        w[k4 * 4 + 0] = t.x;
        w[k4 * 4 + 1] = t.y;
        w[k4 * 4 + 2] = t.z;
        w[k4 * 4 + 3] = t.w;
    }
    float bj = __ldg(b + j);

    const float4* out4 = (const float4*)out;
    int stride = gridDim.x * ROWS_PER_ITER;

    for (int base = blockIdx.x * ROWS_PER_ITER; base < n_nodes; base += stride) {
        // ---- stage 32 rows (512 float4), deg-scaled, MLP=2 ----
        #pragma unroll
        for (int i = 0; i < 2; i++) {
            int idx = tid + i * 256;           // 0..511
            int lr  = idx >> 4;                // local row 0..31
            int k4  = idx & 15;
            int row = base + lr;
            if (row < n_nodes) {
                int d = g_deg[row];            // 16 threads same row -> broadcast
                float invd = (d > 1) ? __frcp_rn((float)d) : 1.0f;
                float4 v = __ldg(out4 + row * 16 + k4);
                v.x *= invd; v.y *= invd; v.z *= invd; v.w *= invd;
                rows4[lr * 16 + k4] = v;
            }
        }
        __syncthreads();

        // ---- compute 8 rows for column j ----
        #pragma unroll
        for (int r = 0; r < ROWS_PER_THREAD; r++) {
            int lr  = g * ROWS_PER_THREAD + r;
            int row = base + lr;
            if (row < n_nodes) {
                float s0 = bj, s1 = 0.f;
                #pragma unroll
                for (int k4 = 0; k4 < 16; k4++) {
                    float4 a = rows4[lr * 16 + k4];    // LDS.128 broadcast
                    s0 = fmaf(a.x, w[k4 * 4 + 0], s0);
                    s1 = fmaf(a.y, w[k4 * 4 + 1], s1);
                    s0 = fmaf(a.z, w[k4 * 4 + 2], s0);
                    s1 = fmaf(a.w, w[k4 * 4 + 3], s1);
                }
                out[row * DIM + j] = s0 + s1;          // coalesced 128B/warp
            }
        }
        __syncthreads();
    }
}

// ---------------------------------------------------------------------------
// Launcher
// ---------------------------------------------------------------------------
extern "C" void kernel_launch(void* const* d_in, const int* in_sizes, int n_in,
                              void* d_out, int out_size)
{
    const float* x  = (const float*)d_in[0];        // [n_nodes, 64]
    const void*  ei = d_in[1];                      // [2, n_edges] int32 or int64
    const float* W  = (const float*)d_in[2];        // [64, 64]
    const float* b  = (const float*)d_in[3];        // [64]
    float*       out = (float*)d_out;               // [n_nodes, 64]

    int n_nodes = in_sizes[0] / DIM;
    int n_edges = in_sizes[1] / 2;

    // 0) dtype sniff
    sniff_kernel<<<1, 32>>>((const int*)ei);

    // 1) zero accumulator + degrees
    int n4 = n_nodes * (DIM / 4);
    {
        int threads = 256;
        int blocks = (n4 + threads - 1) / threads;
        zero_kernel<<<blocks, threads>>>((float4*)out, n4, n_nodes);
    }

    // 2) edge scatter
    {
        long long total = (long long)n_edges * 16;
        int threads = 256;
        int blocks = (int)((total + threads - 1) / threads);
        edge_scatter_kernel<<<blocks, threads>>>(
            ei, (const float4*)x, (float4*)out, n_edges);
    }

    // 3) transform (in-place on d_out)
    {
        int threads = 256;
        int blocks = 592;          // ~4 waves of 2-resident blocks, ~5 iters each
        transform_kernel<<<blocks, threads>>>(out, W, b, n_nodes);
    }
}

// round 13
// speedup vs baseline: 1.4137x; 1.0502x over previous
#include <cuda_runtime.h>
#include <cuda_bf16.h>
#include <cstdint>

// GCN layer: out = (scatter_mean(x[col] -> row)) @ W^T + b
// N_NODES=100000, N_EDGES=1600000, IN=OUT=64
//
// Strategy: build CSR (row -> cols) on device, then one fused kernel does
// gather + mean + (W^T,b) transform. Kills the 410MB of atomic-reduction
// traffic the scatter formulation needed.

#define DIM 64
#define MAX_NODES 100000
#define MAX_EDGES 1600000
#define SCAN_TPB 512
#define MAX_SCAN_BLOCKS 1024

// device scratch (no allocations allowed)
__device__ int g_deg[MAX_NODES];
__device__ int g_ptr[MAX_NODES + 1];
__device__ int g_cursor[MAX_NODES];
__device__ int g_csr[MAX_EDGES];
__device__ int g_blocksum[MAX_SCAN_BLOCKS];
__device__ int g_idx_is64;   // 1 if edge_index is int64, 0 if int32

// ---------------------------------------------------------------------------
// Kernel 0: sniff edge_index dtype. int64 values < 2^31 have every odd
// 32-bit word == 0; random int32 node ids do not.
// ---------------------------------------------------------------------------
__global__ void sniff_kernel(const int* __restrict__ e_words) {
    if (threadIdx.x == 0 && blockIdx.x == 0) {
        int is64 = 1;
        #pragma unroll
        for (int i = 1; i < 64; i += 2) {
            if (e_words[i] != 0) { is64 = 0; break; }
        }
        g_idx_is64 = is64;
    }
}

__device__ __forceinline__ int load_idx(const void* base, int i) {
    if (g_idx_is64) return (int)__ldg(((const long long*)base) + i);
    return __ldg(((const int*)base) + i);
}

// ---------------------------------------------------------------------------
// CSR build
// ---------------------------------------------------------------------------
__global__ void zero_deg_kernel(int n_nodes) {
    int i = blockIdx.x * blockDim.x + threadIdx.x;
    if (i < n_nodes) g_deg[i] = 0;
}

__global__ void hist_kernel(const void* __restrict__ e_base, int n_edges) {
    int e = blockIdx.x * blockDim.x + threadIdx.x;
    if (e < n_edges) {
        int r = load_idx(e_base, e);
        atomicAdd(&g_deg[r], 1);
    }
}

// per-block totals of deg
__global__ void scan1_kernel(int n_nodes) {
    __shared__ int s[SCAN_TPB];
    int tid = threadIdx.x;
    int i = blockIdx.x * SCAN_TPB + tid;
    s[tid] = (i < n_nodes) ? g_deg[i] : 0;
    __syncthreads();
    for (int off = SCAN_TPB / 2; off > 0; off >>= 1) {
        if (tid < off) s[tid] += s[tid + off];
        __syncthreads();
    }
    if (tid == 0) g_blocksum[blockIdx.x] = s[0];
}

// single block: exclusive scan of block totals; writes grand total to ptr[n]
__global__ void scan2_kernel(int nblocks, int n_nodes) {
    __shared__ int s[MAX_SCAN_BLOCKS];
    int tid = threadIdx.x;   // 1024 threads
    int v = (tid < nblocks) ? g_blocksum[tid] : 0;
    s[tid] = v;
    __syncthreads();
    #pragma unroll
    for (int off = 1; off < MAX_SCAN_BLOCKS; off <<= 1) {
        int t = (tid >= off) ? s[tid - off] : 0;
        __syncthreads();
        s[tid] += t;
        __syncthreads();
    }
    if (tid < nblocks) g_blocksum[tid] = s[tid] - v;   // exclusive
    if (tid == MAX_SCAN_BLOCKS - 1) g_ptr[n_nodes] = s[tid];  // grand total
}

// block-local exclusive scan + block offset -> ptr, cursor
__global__ void scan3_kernel(int n_nodes) {
    __shared__ int s[SCAN_TPB];
    int tid = threadIdx.x;
    int i = blockIdx.x * SCAN_TPB + tid;
    int v = (i < n_nodes) ? g_deg[i] : 0;
    s[tid] = v;
    __syncthreads();
    #pragma unroll
    for (int off = 1; off < SCAN_TPB; off <<= 1) {
        int t = (tid >= off) ? s[tid - off] : 0;
        __syncthreads();
        s[tid] += t;
        __syncthreads();
    }
    int p = g_blocksum[blockIdx.x] + s[tid] - v;   // exclusive prefix
    if (i < n_nodes) {
        g_ptr[i] = p;
        g_cursor[i] = p;
    }
}

__global__ void fill_kernel(const void* __restrict__ e_base, int n_edges) {
    int e = blockIdx.x * blockDim.x + threadIdx.x;
    if (e < n_edges) {
        int r = load_idx(e_base, e);
        int c = load_idx(e_base, n_edges + e);
        int pos = atomicAdd(&g_cursor[r], 1);
        g_csr[pos] = c;
    }
}

// ---------------------------------------------------------------------------
// Fused gather + mean + transform.
// 256 threads: 16 lane-groups of 16 threads gather one node each (lane owns
// one float4 chunk, 4 independent accumulators, MLP=4). Result staged in
// shared (deg-scaled), then register-resident-W GEMV: thread owns output
// column j = tid&63, computes 4 rows per iteration.
// ---------------------------------------------------------------------------
__global__ void __launch_bounds__(256) fused_gcn_kernel(
    const float4* __restrict__ x4,         // [n_nodes][16]
    float* __restrict__ out,               // [n_nodes][64]
    const float* __restrict__ W,           // [64][64] row-major (OUT, IN)
    const float* __restrict__ b,
    int n_nodes)
{
    __shared__ float4 rows4[16 * 16];      // 16 rows x 64 floats = 4KB

    int tid    = threadIdx.x;
    int lane16 = tid & 15;
    int nsub   = tid >> 4;       // node slot 0..15
    int g      = tid >> 6;       // transform group 0..3
    int j      = tid & 63;       // output feature

    // W row j -> registers
    float w[DIM];
    const float4* Wj = (const float4*)(W + j * DIM);
    #pragma unroll
    for (int k4 = 0; k4 < 16; k4++) {
        float4 t = __ldg(Wj + k4);
        w[k4 * 4 + 0] = t.x; w[k4 * 4 + 1] = t.y;
        w[k4 * 4 + 2] = t.z; w[k4 * 4 + 3] = t.w;
    }
    float bj = __ldg(b + j);

    int stride = gridDim.x * 16;
    for (int base = blockIdx.x * 16; base < n_nodes; base += stride) {
        // ---- gather + mean for node (base + nsub) ----
        int node = base + nsub;
        float4 a0 = {0,0,0,0}, a1 = {0,0,0,0}, a2 = {0,0,0,0}, a3 = {0,0,0,0};
        if (node < n_nodes) {
            int s = g_ptr[node];
            int e = g_ptr[node + 1];
            int p = s;
            for (; p + 4 <= e; p += 4) {
                int c0 = __ldg(g_csr + p + 0);
                int c1 = __ldg(g_csr + p + 1);
                int c2 = __ldg(g_csr + p + 2);
                int c3 = __ldg(g_csr + p + 3);
                float4 v0 = __ldg(x4 + c0 * 16 + lane16);
                float4 v1 = __ldg(x4 + c1 * 16 + lane16);
                float4 v2 = __ldg(x4 + c2 * 16 + lane16);
                float4 v3 = __ldg(x4 + c3 * 16 + lane16);
                a0.x += v0.x; a0.y += v0.y; a0.z += v0.z; a0.w += v0.w;
                a1.x += v1.x; a1.y += v1.y; a1.z += v1.z; a1.w += v1.w;
                a2.x += v2.x; a2.y += v2.y; a2.z += v2.z; a2.w += v2.w;
                a3.x += v3.x; a3.y += v3.y; a3.z += v3.z; a3.w += v3.w;
            }
            for (; p < e; p++) {
                int c = __ldg(g_csr + p);
                float4 v = __ldg(x4 + c * 16 + lane16);
                a0.x += v.x; a0.y += v.y; a0.z += v.z; a0.w += v.w;
            }
            int d = e - s;
            float invd = (d > 1) ? __frcp_rn((float)d) : 1.0f;
            a0.x = (a0.x + a1.x + a2.x + a3.x) * invd;
            a0.y = (a0.y + a1.y + a2.y + a3.y) * invd;
            a0.z = (a0.z + a1.z + a2.z + a3.z) * invd;
            a0.w = (a0.w + a1.w + a2.w + a3.w) * invd;
        }
        rows4[nsub * 16 + lane16] = a0;
        __syncthreads();

        // ---- transform: 4 rows per thread ----
        #pragma unroll
        for (int r = 0; r < 4; r++) {
            int lr  = g * 4 + r;
            int row = base + lr;
            if (row < n_nodes) {
                float s0 = bj, s1 = 0.f;
                #pragma unroll
                for (int k4 = 0; k4 < 16; k4++) {
                    float4 a = rows4[lr * 16 + k4];   // LDS.128 broadcast
                    s0 = fmaf(a.x, w[k4 * 4 + 0], s0);
                    s1 = fmaf(a.y, w[k4 * 4 + 1], s1);
                    s0 = fmaf(a.z, w[k4 * 4 + 2], s0);
                    s1 = fmaf(a.w, w[k4 * 4 + 3], s1);
                }
                out[row * DIM + j] = s0 + s1;
            }
        }
        __syncthreads();
    }
}

// ---------------------------------------------------------------------------
// Fallback path (shape variants exceeding static scratch): original
// zero + atomic scatter + transform.
// ---------------------------------------------------------------------------
__global__ void zero_kernel(float4* __restrict__ out4, int n4, int n_nodes) {
    int i = blockIdx.x * blockDim.x + threadIdx.x;
    if (i < n4) out4[i] = make_float4(0.f, 0.f, 0.f, 0.f);
    if (i < n_nodes && n_nodes <= MAX_NODES) g_deg[i] = 0;
}

__global__ void __launch_bounds__(256) edge_scatter_kernel(
    const void* __restrict__ e_base,
    const float4* __restrict__ x4,
    float4* __restrict__ out4,
    int n_edges)
{
    int idx  = blockIdx.x * blockDim.x + threadIdx.x;
    int e    = idx >> 4;
    int lane = idx & 15;
    if (e >= n_edges) return;
    int r = load_idx(e_base, e);
    int c = load_idx(e_base, n_edges + e);
    float4 v = __ldg(x4 + (c * 16 + lane));
    atomicAdd(out4 + (r * 16 + lane), v);
    if (lane == 0) atomicAdd(&g_deg[r], 1);
}

__global__ void __launch_bounds__(256) transform_kernel(
    float* __restrict__ out, const float* __restrict__ W,
    const float* __restrict__ b, int n_nodes)
{
    __shared__ float4 rows4[32 * 16];
    int tid = threadIdx.x;
    int g = tid >> 6, j = tid & 63;
    float w[DIM];
    const float4* Wj = (const float4*)(W + j * DIM);
    #pragma unroll
    for (int k4 = 0; k4 < 16; k4++) {
        float4 t = __ldg(Wj + k4);
        w[k4*4+0]=t.x; w[k4*4+1]=t.y; w[k4*4+2]=t.z; w[k4*4+3]=t.w;
    }
    float bj = __ldg(b + j);
    const float4* out4 = (const float4*)out;
    int stride = gridDim.x * 32;
    for (int base = blockIdx.x * 32; base < n_nodes; base += stride) {
        #pragma unroll
        for (int i = 0; i < 2; i++) {
            int idx = tid + i * 256;
            int lr = idx >> 4, k4 = idx & 15;
            int row = base + lr;
            if (row < n_nodes) {
                int d = g_deg[row];
                float invd = (d > 1) ? __frcp_rn((float)d) : 1.0f;
                float4 v = __ldg(out4 + row * 16 + k4);
                v.x*=invd; v.y*=invd; v.z*=invd; v.w*=invd;
                rows4[lr * 16 + k4] = v;
            }
        }
        __syncthreads();
        #pragma unroll
        for (int r = 0; r < 8; r++) {
            int lr = g * 8 + r;
            int row = base + lr;
            if (row < n_nodes) {
                float s0 = bj, s1 = 0.f;
                #pragma unroll
                for (int k4 = 0; k4 < 16; k4++) {
                    float4 a = rows4[lr * 16 + k4];
                    s0 = fmaf(a.x, w[k4*4+0], s0);
                    s1 = fmaf(a.y, w[k4*4+1], s1);
                    s0 = fmaf(a.z, w[k4*4+2], s0);
                    s1 = fmaf(a.w, w[k4*4+3], s1);
                }
                out[row * DIM + j] = s0 + s1;
            }
        }
        __syncthreads();
    }
}

// ---------------------------------------------------------------------------
// Launcher
// ---------------------------------------------------------------------------
extern "C" void kernel_launch(void* const* d_in, const int* in_sizes, int n_in,
                              void* d_out, int out_size)
{
    const float* x  = (const float*)d_in[0];
    const void*  ei = d_in[1];
    const float* W  = (const float*)d_in[2];
    const float* b  = (const float*)d_in[3];
    float*       out = (float*)d_out;

    int n_nodes = in_sizes[0] / DIM;
    int n_edges = in_sizes[1] / 2;

    sniff_kernel<<<1, 32>>>((const int*)ei);

    int nblocks_scan = (n_nodes + SCAN_TPB - 1) / SCAN_TPB;
    bool csr_ok = (n_nodes <= MAX_NODES) && (n_edges <= MAX_EDGES) &&
                  (nblocks_scan <= MAX_SCAN_BLOCKS);

    if (csr_ok) {
        // --- CSR build ---
        zero_deg_kernel<<<(n_nodes + 255) / 256, 256>>>(n_nodes);
        hist_kernel<<<(n_edges + 255) / 256, 256>>>(ei, n_edges);
        scan1_kernel<<<nblocks_scan, SCAN_TPB>>>(n_nodes);
        scan2_kernel<<<1, MAX_SCAN_BLOCKS>>>(nblocks_scan, n_nodes);
        scan3_kernel<<<nblocks_scan, SCAN_TPB>>>(n_nodes);
        fill_kernel<<<(n_edges + 255) / 256, 256>>>(ei, n_edges);
        // --- fused gather + mean + transform ---
        fused_gcn_kernel<<<592, 256>>>((const float4*)x, out, W, b, n_nodes);
    } else {
        int n4 = n_nodes * (DIM / 4);
        zero_kernel<<<(n4 + 255) / 256, 256>>>((float4*)out, n4, n_nodes);
        long long total = (long long)n_edges * 16;
        edge_scatter_kernel<<<(int)((total + 255) / 256), 256>>>(
            ei, (const float4*)x, (float4*)out, n_edges);
        transform_kernel<<<592, 256>>>(out, W, b, n_nodes);
    }
}

// round 14
// speedup vs baseline: 1.8323x; 1.2961x over previous
#include <cuda_runtime.h>
#include <cuda_fp16.h>
#include <cuda_bf16.h>
#include <cstdint>

// GCN layer: out = (scatter_mean(x[col] -> row)) @ W^T + b
//          = scatter_mean( (x @ W^T)[col] -> row ) + b      (linearity)
// Pipeline: CSR build -> dense GEMM y=x@W^T (fp16 out) -> gather-mean(+b).

#define DIM 64
#define MAX_NODES 100000
#define MAX_EDGES 1600000
#define SCAN_TPB 512
#define MAX_SCAN_BLOCKS 1024

// device scratch (no allocations allowed)
__device__ int    g_deg[MAX_NODES];
__device__ int    g_ptr[MAX_NODES + 1];
__device__ int    g_cursor[MAX_NODES];
__device__ int    g_csr[MAX_EDGES];
__device__ int    g_blocksum[MAX_SCAN_BLOCKS];
__device__ __half g_y[MAX_NODES * DIM];        // 12.8 MB fp16 transformed features
__device__ int    g_idx_is64;

// ---------------------------------------------------------------------------
// Kernel 0: sniff edge_index dtype + zero degree array.
// int64 values < 2^31 have every odd 32-bit word == 0.
// ---------------------------------------------------------------------------
__global__ void sniff_zero_kernel(const int* __restrict__ e_words, int n_nodes) {
    int i = blockIdx.x * blockDim.x + threadIdx.x;
    if (i < n_nodes) g_deg[i] = 0;
    if (i == 0) {
        int is64 = 1;
        #pragma unroll
        for (int k = 1; k < 64; k += 2) {
            if (e_words[k] != 0) { is64 = 0; break; }
        }
        g_idx_is64 = is64;
    }
}

__device__ __forceinline__ int load_idx(const void* base, int i) {
    if (g_idx_is64) return (int)__ldg(((const long long*)base) + i);
    return __ldg(((const int*)base) + i);
}

// ---------------------------------------------------------------------------
// CSR build
// ---------------------------------------------------------------------------
__global__ void hist_kernel(const void* __restrict__ e_base, int n_edges) {
    int e = blockIdx.x * blockDim.x + threadIdx.x;
    if (e < n_edges) {
        int r = load_idx(e_base, e);
        atomicAdd(&g_deg[r], 1);
    }
}

__global__ void scan1_kernel(int n_nodes) {
    __shared__ int s[SCAN_TPB];
    int tid = threadIdx.x;
    int i = blockIdx.x * SCAN_TPB + tid;
    s[tid] = (i < n_nodes) ? g_deg[i] : 0;
    __syncthreads();
    for (int off = SCAN_TPB / 2; off > 0; off >>= 1) {
        if (tid < off) s[tid] += s[tid + off];
        __syncthreads();
    }
    if (tid == 0) g_blocksum[blockIdx.x] = s[0];
}

__global__ void scan2_kernel(int nblocks, int n_nodes) {
    __shared__ int s[MAX_SCAN_BLOCKS];
    int tid = threadIdx.x;   // 1024 threads
    int v = (tid < nblocks) ? g_blocksum[tid] : 0;
    s[tid] = v;
    __syncthreads();
    #pragma unroll
    for (int off = 1; off < MAX_SCAN_BLOCKS; off <<= 1) {
        int t = (tid >= off) ? s[tid - off] : 0;
        __syncthreads();
        s[tid] += t;
        __syncthreads();
    }
    if (tid < nblocks) g_blocksum[tid] = s[tid] - v;        // exclusive
    if (tid == MAX_SCAN_BLOCKS - 1) g_ptr[n_nodes] = s[tid];
}

__global__ void scan3_kernel(int n_nodes) {
    __shared__ int s[SCAN_TPB];
    int tid = threadIdx.x;
    int i = blockIdx.x * SCAN_TPB + tid;
    int v = (i < n_nodes) ? g_deg[i] : 0;
    s[tid] = v;
    __syncthreads();
    #pragma unroll
    for (int off = 1; off < SCAN_TPB; off <<= 1) {
        int t = (tid >= off) ? s[tid - off] : 0;
        __syncthreads();
        s[tid] += t;
        __syncthreads();
    }
    int p = g_blocksum[blockIdx.x] + s[tid] - v;
    if (i < n_nodes) {
        g_ptr[i] = p;
        g_cursor[i] = p;
    }
}

__global__ void fill_kernel(const void* __restrict__ e_base, int n_edges) {
    int e = blockIdx.x * blockDim.x + threadIdx.x;
    if (e < n_edges) {
        int r = load_idx(e_base, e);
        int c = load_idx(e_base, n_edges + e);
        int pos = atomicAdd(&g_cursor[r], 1);
        g_csr[pos] = c;
    }
}

// ---------------------------------------------------------------------------
// GEMM: y = x @ W^T  (fp16 output, NO bias — bias added in gather).
// Register-resident W (thread owns col j = tid&63), 32 rows staged/iter.
// ---------------------------------------------------------------------------
__global__ void __launch_bounds__(256) gemm_y_kernel(
    const float4* __restrict__ x4,         // [n_nodes][16]
    const float* __restrict__ W,           // [64][64] row-major (OUT, IN)
    int n_nodes)
{
    __shared__ float4 rows4[32 * 16];      // 8 KB

    int tid = threadIdx.x;
    int g   = tid >> 6;
    int j   = tid & 63;

    float w[DIM];
    const float4* Wj = (const float4*)(W + j * DIM);
    #pragma unroll
    for (int k4 = 0; k4 < 16; k4++) {
        float4 t = __ldg(Wj + k4);
        w[k4*4+0] = t.x; w[k4*4+1] = t.y; w[k4*4+2] = t.z; w[k4*4+3] = t.w;
    }

    int stride = gridDim.x * 32;
    for (int base = blockIdx.x * 32; base < n_nodes; base += stride) {
        #pragma unroll
        for (int i = 0; i < 2; i++) {
            int idx = tid + i * 256;
            int lr = idx >> 4, k4 = idx & 15;
            int row = base + lr;
            if (row < n_nodes) rows4[lr * 16 + k4] = __ldg(x4 + row * 16 + k4);
        }
        __syncthreads();
        #pragma unroll
        for (int r = 0; r < 8; r++) {
            int lr  = g * 8 + r;
            int row = base + lr;
            if (row < n_nodes) {
                float s0 = 0.f, s1 = 0.f;
                #pragma unroll
                for (int k4 = 0; k4 < 16; k4++) {
                    float4 a = rows4[lr * 16 + k4];
                    s0 = fmaf(a.x, w[k4*4+0], s0);
                    s1 = fmaf(a.y, w[k4*4+1], s1);
                    s0 = fmaf(a.z, w[k4*4+2], s0);
                    s1 = fmaf(a.w, w[k4*4+3], s1);
                }
                g_y[row * DIM + j] = __float2half(s0 + s1);
            }
        }
        __syncthreads();
    }
}

// ---------------------------------------------------------------------------
// Gather-mean: out[node] = mean_{c in csr[node]}( y[c] ) + b
// 8 lanes per node; lane owns 16B (8 halves) of the row. No shared, no syncs.
// fp32 accumulation, unroll-4 (MLP=4).
// ---------------------------------------------------------------------------
__global__ void __launch_bounds__(256) gather_mean_kernel(
    float* __restrict__ out,               // [n_nodes][64]
    const float* __restrict__ b,
    int n_nodes)
{
    int t    = blockIdx.x * blockDim.x + threadIdx.x;
    int node = t >> 3;
    int lane = t & 7;
    if (node >= n_nodes) return;

    const uint4* y4 = (const uint4*)g_y;   // 16B = 8 halves; row = 8 uint4

    int s = __ldg(&g_ptr[node]);
    int e = __ldg(&g_ptr[node + 1]);

    float acc[8] = {0,0,0,0,0,0,0,0};

    int p = s;
    for (; p + 4 <= e; p += 4) {
        int c0 = __ldg(g_csr + p + 0);
        int c1 = __ldg(g_csr + p + 1);
        int c2 = __ldg(g_csr + p + 2);
        int c3 = __ldg(g_csr + p + 3);
        uint4 v0 = __ldg(y4 + c0 * 8 + lane);
        uint4 v1 = __ldg(y4 + c1 * 8 + lane);
        uint4 v2 = __ldg(y4 + c2 * 8 + lane);
        uint4 v3 = __ldg(y4 + c3 * 8 + lane);
        #pragma unroll
        for (int q = 0; q < 4; q++) {
            uint32_t u0 = (&v0.x)[q], u1 = (&v1.x)[q], u2 = (&v2.x)[q], u3 = (&v3.x)[q];
            float2 f0 = __half22float2(*(const __half2*)&u0);
            float2 f1 = __half22float2(*(const __half2*)&u1);
            float2 f2 = __half22float2(*(const __half2*)&u2);
            float2 f3 = __half22float2(*(const __half2*)&u3);
            acc[q*2+0] += (f0.x + f1.x) + (f2.x + f3.x);
            acc[q*2+1] += (f0.y + f1.y) + (f2.y + f3.y);
        }
    }
    for (; p < e; p++) {
        int c = __ldg(g_csr + p);
        uint4 v = __ldg(y4 + c * 8 + lane);
        #pragma unroll
        for (int q = 0; q < 4; q++) {
            uint32_t u = (&v.x)[q];
            float2 f = __half22float2(*(const __half2*)&u);
            acc[q*2+0] += f.x;
            acc[q*2+1] += f.y;
        }
    }

    int d = e - s;
    float invd = (d > 1) ? __frcp_rn((float)d) : 1.0f;
    float4 b0 = __ldg((const float4*)b + lane * 2 + 0);
    float4 b1 = __ldg((const float4*)b + lane * 2 + 1);

    float4 o0, o1;
    o0.x = fmaf(acc[0], invd, b0.x);
    o0.y = fmaf(acc[1], invd, b0.y);
    o0.z = fmaf(acc[2], invd, b0.z);
    o0.w = fmaf(acc[3], invd, b0.w);
    o1.x = fmaf(acc[4], invd, b1.x);
    o1.y = fmaf(acc[5], invd, b1.y);
    o1.z = fmaf(acc[6], invd, b1.z);
    o1.w = fmaf(acc[7], invd, b1.w);

    float4* outv = (float4*)(out + node * DIM + lane * 8);
    outv[0] = o0;
    outv[1] = o1;
}

// ---------------------------------------------------------------------------
// Fallback path (oversized shape variants): zero + atomic scatter + transform.
// ---------------------------------------------------------------------------
__global__ void zero_kernel(float4* __restrict__ out4, int n4, int n_nodes) {
    int i = blockIdx.x * blockDim.x + threadIdx.x;
    if (i < n4) out4[i] = make_float4(0.f, 0.f, 0.f, 0.f);
    if (i < n_nodes && n_nodes <= MAX_NODES) g_deg[i] = 0;
}

__global__ void __launch_bounds__(256) edge_scatter_kernel(
    const void* __restrict__ e_base,
    const float4* __restrict__ x4,
    float4* __restrict__ out4,
    int n_edges)
{
    int idx  = blockIdx.x * blockDim.x + threadIdx.x;
    int e    = idx >> 4;
    int lane = idx & 15;
    if (e >= n_edges) return;
    int r = load_idx(e_base, e);
    int c = load_idx(e_base, n_edges + e);
    float4 v = __ldg(x4 + (c * 16 + lane));
    atomicAdd(out4 + (r * 16 + lane), v);
    if (lane == 0) atomicAdd((int*)&g_deg[r], 1);
}

__global__ void __launch_bounds__(256) transform_kernel(
    float* __restrict__ out, const float* __restrict__ W,
    const float* __restrict__ b, int n_nodes)
{
    __shared__ float4 rows4[32 * 16];
    int tid = threadIdx.x;
    int g = tid >> 6, j = tid & 63;
    float w[DIM];
    const float4* Wj = (const float4*)(W + j * DIM);
    #pragma unroll
    for (int k4 = 0; k4 < 16; k4++) {
        float4 t = __ldg(Wj + k4);
        w[k4*4+0]=t.x; w[k4*4+1]=t.y; w[k4*4+2]=t.z; w[k4*4+3]=t.w;
    }
    float bj = __ldg(b + j);
    const float4* out4 = (const float4*)out;
    int stride = gridDim.x * 32;
    for (int base = blockIdx.x * 32; base < n_nodes; base += stride) {
        #pragma unroll
        for (int i = 0; i < 2; i++) {
            int idx = tid + i * 256;
            int lr = idx >> 4, k4 = idx & 15;
            int row = base + lr;
            if (row < n_nodes) {
                int d = g_deg[row];
                float invd = (d > 1) ? __frcp_rn((float)d) : 1.0f;
                float4 v = __ldg(out4 + row * 16 + k4);
                v.x*=invd; v.y*=invd; v.z*=invd; v.w*=invd;
                rows4[lr * 16 + k4] = v;
            }
        }
        __syncthreads();
        #pragma unroll
        for (int r = 0; r < 8; r++) {
            int lr = g * 8 + r;
            int row = base + lr;
            if (row < n_nodes) {
                float s0 = bj, s1 = 0.f;
                #pragma unroll
                for (int k4 = 0; k4 < 16; k4++) {
                    float4 a = rows4[lr * 16 + k4];
                    s0 = fmaf(a.x, w[k4*4+0], s0);
                    s1 = fmaf(a.y, w[k4*4+1], s1);
                    s0 = fmaf(a.z, w[k4*4+2], s0);
                    s1 = fmaf(a.w, w[k4*4+3], s1);
                }
                out[row * DIM + j] = s0 + s1;
            }
        }
        __syncthreads();
    }
}

// ---------------------------------------------------------------------------
// Launcher
// ---------------------------------------------------------------------------
extern "C" void kernel_launch(void* const* d_in, const int* in_sizes, int n_in,
                              void* d_out, int out_size)
{
    const float* x  = (const float*)d_in[0];
    const void*  ei = d_in[1];
    const float* W  = (const float*)d_in[2];
    const float* b  = (const float*)d_in[3];
    float*       out = (float*)d_out;

    int n_nodes = in_sizes[0] / DIM;
    int n_edges = in_sizes[1] / 2;

    int nblocks_scan = (n_nodes + SCAN_TPB - 1) / SCAN_TPB;
    bool csr_ok = (n_nodes <= MAX_NODES) && (n_edges <= MAX_EDGES) &&
                  (nblocks_scan <= MAX_SCAN_BLOCKS);

    if (csr_ok) {
        // 0) sniff dtype + zero degrees
        sniff_zero_kernel<<<(n_nodes + 255) / 256, 256>>>((const int*)ei, n_nodes);
        // 1) CSR build
        hist_kernel<<<(n_edges + 255) / 256, 256>>>(ei, n_edges);
        scan1_kernel<<<nblocks_scan, SCAN_TPB>>>(n_nodes);
        scan2_kernel<<<1, MAX_SCAN_BLOCKS>>>(nblocks_scan, n_nodes);
        scan3_kernel<<<nblocks_scan, SCAN_TPB>>>(n_nodes);
        fill_kernel<<<(n_edges + 255) / 256, 256>>>(ei, n_edges);
        // 2) dense GEMM y = x @ W^T (fp16 out)  — runs concurrently-ish after fill
        gemm_y_kernel<<<592, 256>>>((const float4*)x, W, n_nodes);
        // 3) gather-mean + bias
        {
            long long total = (long long)n_nodes * 8;
            int blocks = (int)((total + 255) / 256);
            gather_mean_kernel<<<blocks, 256>>>(out, b, n_nodes);
        }
    } else {
        sniff_zero_kernel<<<(n_nodes + 255) / 256, 256>>>((const int*)ei, n_nodes);
        int n4 = n_nodes * (DIM / 4);
        zero_kernel<<<(n4 + 255) / 256, 256>>>((float4*)out, n4, n_nodes);
        long long total = (long long)n_edges * 16;
        edge_scatter_kernel<<<(int)((total + 255) / 256), 256>>>(
            ei, (const float4*)x, (float4*)out, n_edges);
        transform_kernel<<<592, 256>>>(out, W, b, n_nodes);
    }
}